// round 14
// baseline (speedup 1.0000x reference)
#include <cuda_runtime.h>
#include <cuda_fp16.h>

#define N_NODES 200000
#define C_IN 5
#define T_BLK 256

// Per-node packed struct: {.x = half2(h0,h1) bits, .y = cnt}. 8B aligned.
// Invariant across calls (zero-init at load, restored by k_final each call):
//   cnt field == 0, g_acc == 0 at every call entry.
__device__ int2   g_node[N_NODES];
__device__ float2 g_acc[N_NODES];    // edge-sum of h[src]*dinv[src] per dst

__device__ __forceinline__ void red_add_v2(float2* addr, float a, float b) {
    asm volatile("red.global.add.v2.f32 [%0], {%1, %2};"
                 :: "l"(addr), "f"(a), "f"(b)
                 : "memory");
}

__device__ __forceinline__ int4 ldg_cs_int4(const int4* p) {
    int4 v;
    asm volatile("ld.global.cs.v4.s32 {%0,%1,%2,%3}, [%4];"
                 : "=r"(v.x), "=r"(v.y), "=r"(v.z), "=r"(v.w) : "l"(p));
    return v;
}

// Cache-all 8B gather of the node struct.
__device__ __forceinline__ int2 ldg_ca_i2(const int2* p) {
    int2 v;
    asm volatile("ld.global.ca.v2.s32 {%0,%1}, [%2];"
                 : "=r"(v.x), "=r"(v.y) : "l"(p));
    return v;
}

__device__ __forceinline__ unsigned pack_h(float h0, float h1) {
    __half2 hh = __floats2half2_rn(h0, h1);
    return *reinterpret_cast<unsigned*>(&hh);
}

__device__ __forceinline__ float2 unpack_h(int bits) {
    __half2 hh = *reinterpret_cast<__half2*>(&bits);
    return __half22float2(hh);
}

// Pure node kernel: h = x@W -> g_node[].x (half2). Touches ONLY .x words.
__global__ void k_h(const float* __restrict__ x,
                    const float* __restrict__ W, int n) {
    int i = blockIdx.x * blockDim.x + threadIdx.x;
    if (i < n) {
        const float* xr = x + (size_t)i * C_IN;
        float x0 = xr[0], x1 = xr[1], x2 = xr[2], x3 = xr[3], x4 = xr[4];
        float h0 = x0 * W[0] + x1 * W[2] + x2 * W[4] + x3 * W[6] + x4 * W[8];
        float h1 = x0 * W[1] + x1 * W[3] + x2 * W[5] + x3 * W[7] + x4 * W[9];
        g_node[i].x = (int)pack_h(h0, h1);
    }
    cudaTriggerProgrammaticLaunchCompletion();
}

// Pure count kernel: 4 edges/thread, atomics on g_node[].y ONLY.
// Index prefetch pre-sync (pure input, independent of k_h).
__global__ void __launch_bounds__(T_BLK) k_count(const int4* __restrict__ dst4, int E4) {
    int i = blockIdx.x * blockDim.x + threadIdx.x;
    int4 d;
    bool active = (i < E4);
    if (active) d = ldg_cs_int4(dst4 + i);
    cudaGridDependencySynchronize();
    if (active) {
        atomicAdd(&g_node[d.x].y, 1);
        atomicAdd(&g_node[d.y].y, 1);
        atomicAdd(&g_node[d.z].y, 1);
        atomicAdd(&g_node[d.w].y, 1);
    }
    cudaTriggerProgrammaticLaunchCompletion();
}

// 4 edges/thread: ONE 8B struct gather per edge; dinv computed inline;
// fused v2 RED into acc[dst]. PDL-gated on k_count.
__global__ void __launch_bounds__(T_BLK) k_scatter(const int4* __restrict__ src4,
                                                   const int4* __restrict__ dst4,
                                                   int E4) {
    int i = blockIdx.x * blockDim.x + threadIdx.x;
    int4 s, d;
    bool active = (i < E4);
    if (active) {                 // prefetch indices (pure inputs)
        s = ldg_cs_int4(src4 + i);
        d = ldg_cs_int4(dst4 + i);
    }
    cudaGridDependencySynchronize();
    if (active) {
        int2 a = ldg_ca_i2(&g_node[s.x]);
        int2 b = ldg_ca_i2(&g_node[s.y]);
        int2 c = ldg_ca_i2(&g_node[s.z]);
        int2 e = ldg_ca_i2(&g_node[s.w]);
        float2 ha = unpack_h(a.x);
        float2 hb = unpack_h(b.x);
        float2 hc = unpack_h(c.x);
        float2 he = unpack_h(e.x);
        float da = rsqrtf((float)(a.y + 1));
        float db = rsqrtf((float)(b.y + 1));
        float dc = rsqrtf((float)(c.y + 1));
        float de = rsqrtf((float)(e.y + 1));
        red_add_v2(&g_acc[d.x], ha.x * da, ha.y * da);
        red_add_v2(&g_acc[d.y], hb.x * db, hb.y * db);
        red_add_v2(&g_acc[d.z], hc.x * dc, hc.y * dc);
        red_add_v2(&g_acc[d.w], he.x * de, he.y * de);
    }
    cudaTriggerProgrammaticLaunchCompletion();
}

// Finalize: self-loop term added here; resets cnt and acc for next call.
__global__ void k_final(const float* __restrict__ x,
                        const float* __restrict__ b,
                        float* __restrict__ out,
                        int n) {
    int i = blockIdx.x * blockDim.x + threadIdx.x;
    float x0 = 0, x1 = 0, x2 = 0, x3 = 0, x4 = 0, b0 = 0, b1 = 0;
    if (i < n) {
        const float* xr = x + (size_t)i * C_IN;
        x0 = xr[0]; x1 = xr[1]; x2 = xr[2]; x3 = xr[3]; x4 = xr[4];
        b0 = b[0]; b1 = b[1];
    }
    cudaGridDependencySynchronize();
    if (i >= n) return;
    int2 nd = g_node[i];
    float2 a = g_acc[i];
    // restore invariants for the next call
    g_acc[i] = make_float2(0.0f, 0.0f);
    g_node[i].y = 0;
    float2 h = unpack_h(nd.x);
    float dinv = rsqrtf((float)(nd.y + 1));   // +1 self-loop
    // out = dinv * (edge_sum + self_loop h*dinv) + bias
    float sum0 = a.x + h.x * dinv;
    float sum1 = a.y + h.y * dinv;
    float acc0 = (sum0 * dinv + b0) * 0.01f;
    float acc1 = (sum1 * dinv + b1) * 0.01f;
    float v0 = fminf(fmaxf(x2 + acc0, -0.1f), 0.1f);
    float v1 = fminf(fmaxf(x3 + acc1, -0.1f), 0.1f);
    float p0 = fminf(fmaxf(x0 + v0, -1.0f), 1.0f);
    float p1 = fminf(fmaxf(x1 + v1, -1.0f), 1.0f);
    float* orow = out + (size_t)i * C_IN;
    orow[0] = p0;
    orow[1] = p1;
    orow[2] = v0;
    orow[3] = v1;
    orow[4] = x4;
}

template <typename... Args>
static inline void launch_pdl(void (*kern)(Args...), int grid, int block,
                              Args... args) {
    cudaLaunchConfig_t cfg = {};
    cfg.gridDim = dim3(grid);
    cfg.blockDim = dim3(block);
    cudaLaunchAttribute attr[1];
    attr[0].id = cudaLaunchAttributeProgrammaticStreamSerialization;
    attr[0].val.programmaticStreamSerializationAllowed = 1;
    cfg.attrs = attr;
    cfg.numAttrs = 1;
    cudaLaunchKernelEx(&cfg, kern, args...);
}

extern "C" void kernel_launch(void* const* d_in, const int* in_sizes, int n_in,
                              void* d_out, int out_size) {
    const float* x  = (const float*)d_in[0];   // [N,5]
    const int*   ei = (const int*)d_in[1];     // [2,E]: src row then dst row
    const float* W  = (const float*)d_in[2];   // [5,2]
    const float* b  = (const float*)d_in[3];   // [2]
    float* out = (float*)d_out;

    int n = in_sizes[0] / C_IN;     // 200000
    int E = in_sizes[1] / 2;        // 12800000 (divisible by 4)
    const int* src = ei;
    const int* dst = ei + E;
    int E4 = E / 4;

    int gN  = (n + T_BLK - 1) / T_BLK;
    int gE4 = (E4 + T_BLK - 1) / T_BLK;

    k_h<<<gN, T_BLK>>>(x, W, n);
    launch_pdl(k_count, gE4, T_BLK, (const int4*)dst, E4);
    launch_pdl(k_scatter, gE4, T_BLK, (const int4*)src, (const int4*)dst, E4);
    launch_pdl(k_final, gN, T_BLK, x, b, out, n);
}

// round 15
// speedup vs baseline: 1.0119x; 1.0119x over previous
#include <cuda_runtime.h>

#define N_NODES 200000
#define C_IN 5
#define T_BLK 256

// Per-node packed struct: {h0, h1, cnt(int bits), pad}. 16B aligned.
// Invariant across calls (zero-init at load, restored by k_final each call):
//   cnt field == 0, g_acc == 0 at every call entry.
__device__ float4 g_node[N_NODES];
__device__ float2 g_acc[N_NODES];    // edge-sum of h[src]*dinv[src] per dst

__device__ __forceinline__ void red_add_v2(float2* addr, float a, float b) {
    asm volatile("red.global.add.v2.f32 [%0], {%1, %2};"
                 :: "l"(addr), "f"(a), "f"(b)
                 : "memory");
}

__device__ __forceinline__ int4 ldg_cs_int4(const int4* p) {
    int4 v;
    asm volatile("ld.global.cs.v4.s32 {%0,%1,%2,%3}, [%4];"
                 : "=r"(v.x), "=r"(v.y), "=r"(v.z), "=r"(v.w) : "l"(p));
    return v;
}

// Cache-all 16B gather of the node struct.
__device__ __forceinline__ float4 ldg_ca_f4(const float4* p) {
    float4 v;
    asm volatile("ld.global.ca.v4.f32 {%0,%1,%2,%3}, [%4];"
                 : "=f"(v.x), "=f"(v.y), "=f"(v.z), "=f"(v.w) : "l"(p));
    return v;
}

// Hetero grid, COUNT blocks FIRST (saturate atomics immediately); h-blocks
// LAST (they run inside count's drain wave).
//   blocks [0, gE4)       : in-degree RED into g_node[].z, 4 edges/thread
//   blocks [gE4, gE4+gN)  : h = x@W into g_node[].xy (disjoint words)
__global__ void __launch_bounds__(T_BLK) k_count_h(const int4* __restrict__ dst4, int E4,
                                                   const float* __restrict__ x,
                                                   const float* __restrict__ W,
                                                   int n, int gE4) {
    if (blockIdx.x < (unsigned)gE4) {
        int i = blockIdx.x * T_BLK + threadIdx.x;
        if (i < E4) {
            int4 d = ldg_cs_int4(dst4 + i);
            atomicAdd((int*)&g_node[d.x].z, 1);
            atomicAdd((int*)&g_node[d.y].z, 1);
            atomicAdd((int*)&g_node[d.z].z, 1);
            atomicAdd((int*)&g_node[d.w].z, 1);
        }
    } else {
        int i = (blockIdx.x - gE4) * T_BLK + threadIdx.x;
        if (i < n) {
            const float* xr = x + (size_t)i * C_IN;
            float x0 = xr[0], x1 = xr[1], x2 = xr[2], x3 = xr[3], x4 = xr[4];
            float h0 = x0 * W[0] + x1 * W[2] + x2 * W[4] + x3 * W[6] + x4 * W[8];
            float h1 = x0 * W[1] + x1 * W[3] + x2 * W[5] + x3 * W[7] + x4 * W[9];
            *(float2*)&g_node[i] = make_float2(h0, h1);   // .xy only
        }
    }
    cudaTriggerProgrammaticLaunchCompletion();
}

// 4 edges/thread: ONE 16B struct gather per edge; dinv computed inline;
// fused v2 RED into acc[dst]. PDL-gated on k_count_h.
__global__ void __launch_bounds__(T_BLK) k_scatter(const int4* __restrict__ src4,
                                                   const int4* __restrict__ dst4,
                                                   int E4) {
    int i = blockIdx.x * blockDim.x + threadIdx.x;
    int4 s, d;
    bool active = (i < E4);
    if (active) {                 // prefetch indices (pure inputs)
        s = ldg_cs_int4(src4 + i);
        d = ldg_cs_int4(dst4 + i);
    }
    cudaGridDependencySynchronize();
    if (active) {
        float4 a = ldg_ca_f4(&g_node[s.x]);
        float4 b = ldg_ca_f4(&g_node[s.y]);
        float4 c = ldg_ca_f4(&g_node[s.z]);
        float4 e = ldg_ca_f4(&g_node[s.w]);
        float da = rsqrtf((float)(__float_as_int(a.z) + 1));
        float db = rsqrtf((float)(__float_as_int(b.z) + 1));
        float dc = rsqrtf((float)(__float_as_int(c.z) + 1));
        float de = rsqrtf((float)(__float_as_int(e.z) + 1));
        red_add_v2(&g_acc[d.x], a.x * da, a.y * da);
        red_add_v2(&g_acc[d.y], b.x * db, b.y * db);
        red_add_v2(&g_acc[d.z], c.x * dc, c.y * dc);
        red_add_v2(&g_acc[d.w], e.x * de, e.y * de);
    }
    cudaTriggerProgrammaticLaunchCompletion();
}

// Finalize: self-loop term added here; resets cnt and acc for next call.
// Output rows written with streaming stores (one-touch).
__global__ void k_final(const float* __restrict__ x,
                        const float* __restrict__ b,
                        float* __restrict__ out,
                        int n) {
    int i = blockIdx.x * blockDim.x + threadIdx.x;
    float x0 = 0, x1 = 0, x2 = 0, x3 = 0, x4 = 0, b0 = 0, b1 = 0;
    if (i < n) {
        const float* xr = x + (size_t)i * C_IN;
        x0 = xr[0]; x1 = xr[1]; x2 = xr[2]; x3 = xr[3]; x4 = xr[4];
        b0 = b[0]; b1 = b[1];
    }
    cudaGridDependencySynchronize();
    if (i >= n) return;
    float4 nd = g_node[i];
    float2 a = g_acc[i];
    // restore invariants for the next call
    g_acc[i] = make_float2(0.0f, 0.0f);
    *(int*)&g_node[i].z = 0;
    float dinv = rsqrtf((float)(__float_as_int(nd.z) + 1));   // +1 self-loop
    float sum0 = a.x + nd.x * dinv;
    float sum1 = a.y + nd.y * dinv;
    float acc0 = (sum0 * dinv + b0) * 0.01f;
    float acc1 = (sum1 * dinv + b1) * 0.01f;
    float v0 = fminf(fmaxf(x2 + acc0, -0.1f), 0.1f);
    float v1 = fminf(fmaxf(x3 + acc1, -0.1f), 0.1f);
    float p0 = fminf(fmaxf(x0 + v0, -1.0f), 1.0f);
    float p1 = fminf(fmaxf(x1 + v1, -1.0f), 1.0f);
    float* orow = out + (size_t)i * C_IN;
    asm volatile("st.global.cs.f32 [%0], %1;"      :: "l"(orow + 0), "f"(p0) : "memory");
    asm volatile("st.global.cs.f32 [%0], %1;"      :: "l"(orow + 1), "f"(p1) : "memory");
    asm volatile("st.global.cs.f32 [%0], %1;"      :: "l"(orow + 2), "f"(v0) : "memory");
    asm volatile("st.global.cs.f32 [%0], %1;"      :: "l"(orow + 3), "f"(v1) : "memory");
    asm volatile("st.global.cs.f32 [%0], %1;"      :: "l"(orow + 4), "f"(x4) : "memory");
}

template <typename... Args>
static inline void launch_pdl(void (*kern)(Args...), int grid, int block,
                              Args... args) {
    cudaLaunchConfig_t cfg = {};
    cfg.gridDim = dim3(grid);
    cfg.blockDim = dim3(block);
    cudaLaunchAttribute attr[1];
    attr[0].id = cudaLaunchAttributeProgrammaticStreamSerialization;
    attr[0].val.programmaticStreamSerializationAllowed = 1;
    cfg.attrs = attr;
    cfg.numAttrs = 1;
    cudaLaunchKernelEx(&cfg, kern, args...);
}

extern "C" void kernel_launch(void* const* d_in, const int* in_sizes, int n_in,
                              void* d_out, int out_size) {
    const float* x  = (const float*)d_in[0];   // [N,5]
    const int*   ei = (const int*)d_in[1];     // [2,E]: src row then dst row
    const float* W  = (const float*)d_in[2];   // [5,2]
    const float* b  = (const float*)d_in[3];   // [2]
    float* out = (float*)d_out;

    int n = in_sizes[0] / C_IN;     // 200000
    int E = in_sizes[1] / 2;        // 12800000 (divisible by 4)
    const int* src = ei;
    const int* dst = ei + E;
    int E4 = E / 4;

    int gN  = (n + T_BLK - 1) / T_BLK;
    int gE4 = (E4 + T_BLK - 1) / T_BLK;

    k_count_h<<<gE4 + gN, T_BLK>>>((const int4*)dst, E4, x, W, n, gE4);
    launch_pdl(k_scatter, gE4, T_BLK, (const int4*)src, (const int4*)dst, E4);
    launch_pdl(k_final, gN, T_BLK, x, b, out, n);
}